// round 15
// baseline (speedup 1.0000x reference)
#include <cuda_runtime.h>
#include <cuda_bf16.h>
#include <cstdint>

// ---------------------------------------------------------------------------
// ProxyNCALoss on GB300 — HMMA path (ptxas stage targets sm_103: no tcgen05).
//   loss_b = d_pos[b] + log( exp(-xsq_b - 1) * (S_b - 32) - exp(-d_pos_b) )
// GEMM M=1024, N=100032 (1563 x 64), K=128, bf16 mma.sync.
// R15 = R14 + PERSISTENT CTAs (grid 296, 2/SM): each CTA walks 5-6 N-tiles;
// next tile's fp32 proxies are cp.async-staged into smem during iter 8 of the
// current tile and normalized from smem at the boundary — B DRAM latency and
// wave transitions are hidden behind the mainloop.
// ---------------------------------------------------------------------------

#define C_CLS 100000
#define D_DIM 128
#define B_ROWS 1024

constexpr int BN = 64;
constexpr int NTILES = (C_CLS + BN - 1) / BN;   // 1563
constexpr int N_PADS = NTILES * BN - C_CLS;     // 32
constexpr int W_ITERS = 16;
constexpr int GRID_G  = 296;                    // 2 CTAs/SM on 148 SMs
constexpr int SLICES  = 16;
constexpr int RED_SLICE_BLKS = 32 * SLICES;     // 512
constexpr int RED_POS_BLKS   = 128;
constexpr int RED_TOTAL_BLKS = RED_SLICE_BLKS + RED_POS_BLKS;   // 640

constexpr int LDSB = 136;                       // B smem row pitch (bf16 elems)
constexpr int A_PBUF = 16 * 256;                // 4096
constexpr int A_PREGION = 2 * A_PBUF;           // 8192
constexpr int SMEM_B_OFF     = 4 * A_PREGION;   // 32768
constexpr int SMEM_STAGE_OFF = SMEM_B_OFF + BN * LDSB * 2;   // 50176
constexpr int SMEM_TOTAL     = SMEM_STAGE_OFF + BN * D_DIM * 4;  // 82944

constexpr float TWO_LOG2E = 2.8853900817779268f;  // 2*log2(e)

// ------------------------- device scratch ----------------------------------
__device__ __nv_bfloat16 g_X[B_ROWS * D_DIM];
__device__ float g_partA[(size_t)NTILES * B_ROWS];   // [tile][b], cols 0-31
__device__ float g_partB[(size_t)NTILES * B_ROWS];   // [tile][b], cols 32-63
__device__ float g_stage[SLICES][B_ROWS];
__device__ float g_dpos[B_ROWS];
__device__ float g_xsq[B_ROWS];
__device__ int   g_cnt;

// ------------------------- helpers -----------------------------------------
__device__ __forceinline__ float warp_sum(float v) {
#pragma unroll
    for (int m = 16; m > 0; m >>= 1) v += __shfl_xor_sync(0xFFFFFFFFu, v, m);
    return v;
}
__device__ __forceinline__ float ex2_approx(float x) {
    float r;
    asm("ex2.approx.f32 %0, %1;" : "=f"(r) : "f"(x));
    return r;
}
__device__ __forceinline__ void cp_async16(uint32_t dst, const void* src) {
    asm volatile("cp.async.cg.shared.global [%0], [%1], 16;" :: "r"(dst), "l"(src));
}
#define CP_COMMIT() asm volatile("cp.async.commit_group;" ::: "memory")
#define CP_WAIT0()  asm volatile("cp.async.wait_group 0;" ::: "memory")
#define BAR_PAIR(id) asm volatile("bar.sync %0, 64;" :: "r"(id) : "memory")

#define LDSM_X4(r0, r1, r2, r3, addr) \
    asm volatile("ldmatrix.sync.aligned.m8n8.x4.shared.b16 {%0,%1,%2,%3}, [%4];\n" \
                 : "=r"(r0), "=r"(r1), "=r"(r2), "=r"(r3) : "r"(addr))

#define MMA16816(acc, a0, a1, a2, a3, b0, b1) \
    asm volatile("mma.sync.aligned.m16n8k16.row.col.f32.bf16.bf16.f32 " \
                 "{%0,%1,%2,%3}, {%4,%5,%6,%7}, {%8,%9}, {%0,%1,%2,%3};\n" \
                 : "+f"((acc)[0]), "+f"((acc)[1]), "+f"((acc)[2]), "+f"((acc)[3]) \
                 : "r"(a0), "r"(a1), "r"(a2), "r"(a3), "r"(b0), "r"(b1))

// ------------------------- pre-kernel: xs -> bf16 only ----------------------
__global__ void pre_kernel(const float* __restrict__ xs) {
    if (blockIdx.x == 0 && threadIdx.x == 0) g_cnt = 0;
    int i = blockIdx.x * blockDim.x + threadIdx.x;
    float4 v = reinterpret_cast<const float4*>(xs)[i];
    __nv_bfloat162 lo = __floats2bfloat162_rn(v.x, v.y);
    __nv_bfloat162 hi = __floats2bfloat162_rn(v.z, v.w);
    reinterpret_cast<__nv_bfloat162*>(g_X)[2 * i]     = lo;
    reinterpret_cast<__nv_bfloat162*>(g_X)[2 * i + 1] = hi;
}

// normalize 8 fp32 rows (held in v[8]) and write bf16 into sB (scaled 2log2e)
__device__ __forceinline__ void build_sB_rows(__nv_bfloat16* sB, float4* v,
                                              int r0, int nbase, int lane) {
#pragma unroll
    for (int i = 0; i < 8; i++) {
        const int gr = nbase + r0 + i;
        float sq = warp_sum(v[i].x*v[i].x + v[i].y*v[i].y + v[i].z*v[i].z + v[i].w*v[i].w);
        float rn = TWO_LOG2E * rsqrtf(fmaxf(sq, 1e-24f));
        if (gr >= C_CLS) rn = 0.0f;
        __nv_bfloat162 lo = __floats2bfloat162_rn(v[i].x * rn, v[i].y * rn);
        __nv_bfloat162 hi = __floats2bfloat162_rn(v[i].z * rn, v[i].w * rn);
        uint2 u;
        u.x = *reinterpret_cast<uint32_t*>(&lo);
        u.y = *reinterpret_cast<uint32_t*>(&hi);
        *reinterpret_cast<uint2*>(&sB[(r0 + i) * LDSB + lane * 4]) = u;
    }
}

// ------------------------- GEMM + exp2 row-sum ------------------------------
__global__ __launch_bounds__(256, 2) void gemm_kernel(const float* __restrict__ proxies) {
    extern __shared__ __align__(16) char smem[];
    __nv_bfloat16* sB = reinterpret_cast<__nv_bfloat16*>(smem + SMEM_B_OFF);
    char* stage = smem + SMEM_STAGE_OFF;
    const uint32_t sbase = (uint32_t)__cvta_generic_to_shared(smem);

    const int tid  = threadIdx.x;
    const int wid  = tid >> 5;
    const int lane = tid & 31;

    const int pair  = wid >> 1;
    const int half  = wid & 1;
    const int mwarp = pair * 16;
    const int ncb   = half * 32;
    const int barid = pair + 1;
    float* gpartbase = (half ? g_partB : g_partA);

    const uint32_t ap_base = sbase + pair * A_PREGION;
    const int r0 = wid * 8;                     // this warp's B rows

    // ---- prologue: A tile 0 half + first tile's B from gmem ----
    {
        const char* gA = reinterpret_cast<const char*>(g_X) + (size_t)mwarp * 256;
#pragma unroll
        for (int j = 0; j < 4; j++) {
            int idx = lane + 32 * j;
            int r = half * 8 + (idx >> 4);
            int c = idx & 15;
            cp_async16(ap_base + r * 256 + ((c ^ (r & 7)) * 16), gA + r * 256 + c * 16);
        }
        CP_COMMIT();
    }
    {
        const int nbase0 = blockIdx.x * BN;
        float4 v[8];
#pragma unroll
        for (int i = 0; i < 8; i++) {
            const int gr = nbase0 + r0 + i;
            if (gr < C_CLS) v[i] = reinterpret_cast<const float4*>(proxies + (size_t)gr * D_DIM)[lane];
            else            v[i] = make_float4(0.f, 0.f, 0.f, 0.f);
        }
        build_sB_rows(sB, v, r0, nbase0, lane);
    }
    __syncthreads();

    const int bRowOff = (lane & 7) + ((lane >> 4) << 3);
    const int bColOff = ((lane >> 3) & 1) * 8;
    const int aRow = lane & 15;
    const int aChunkHalf = lane >> 4;

    uint32_t breg[2][8][4];
#pragma unroll
    for (int g = 0; g < 2; g++)
#pragma unroll
        for (int k = 0; k < 8; k++) {
            uint32_t addrB = (uint32_t)__cvta_generic_to_shared(
                &sB[(ncb + g * 16 + bRowOff) * LDSB + k * 16 + bColOff]);
            LDSM_X4(breg[g][k][0], breg[g][k][1], breg[g][k][2], breg[g][k][3], addrB);
        }

    // ================= persistent tile loop =================
#pragma unroll 1
    for (int nt = blockIdx.x; nt < NTILES; nt += GRID_G) {
        const bool last_tile = (nt + GRID_G >= NTILES);
        float* gpart = gpartbase + (size_t)nt * B_ROWS;

#pragma unroll 1
        for (int it = 0; it < W_ITERS; it++) {
            const int buf = it & 1;
            CP_WAIT0();
            __syncwarp();
            BAR_PAIR(barid);       // acquire

            // A prefetch: next iter, or next tile's iter0 (same rows 0..63)
            {
                int next_m = (it + 1 < W_ITERS) ? (it + 1) * 64 + mwarp : mwarp;
                if (it + 1 < W_ITERS || !last_tile) {
                    const char* gA = reinterpret_cast<const char*>(g_X) + (size_t)next_m * 256;
                    const uint32_t dst = ap_base + (buf ^ 1) * A_PBUF;
#pragma unroll
                    for (int j = 0; j < 4; j++) {
                        int idx = lane + 32 * j;
                        int r = half * 8 + (idx >> 4);
                        int c = idx & 15;
                        cp_async16(dst + r * 256 + ((c ^ (r & 7)) * 16), gA + r * 256 + c * 16);
                    }
                }
                // stage next tile's fp32 proxies at iter 8 (joins this group;
                // its wait lands one full iter later > DRAM latency)
                if (it == 8 && !last_tile) {
                    const int nb2 = (nt + GRID_G) * BN;
#pragma unroll
                    for (int i = 0; i < 8; i++) {
                        const int gr = nb2 + r0 + i;
                        if (gr < C_CLS)
                            cp_async16((uint32_t)__cvta_generic_to_shared(
                                           stage + (r0 + i) * 512 + lane * 16),
                                       proxies + (size_t)gr * D_DIM + lane * 4);
                    }
                }
                CP_COMMIT();
            }

            const uint32_t abuf = ap_base + buf * A_PBUF;

            float acc[4][4];
#pragma unroll
            for (int nf = 0; nf < 4; nf++)
#pragma unroll
                for (int j = 0; j < 4; j++) acc[nf][j] = 0.0f;

            // ---- phase 1: g=0 MMA chain ----
#pragma unroll
            for (int k = 0; k < 8; k++) {
                const int c = 2 * k + aChunkHalf;
                uint32_t a0, a1, a2, a3;
                uint32_t addrA = abuf + aRow * 256 + ((c ^ (aRow & 7)) * 16);
                LDSM_X4(a0, a1, a2, a3, addrA);
                MMA16816(acc[0], a0, a1, a2, a3, breg[0][k][0], breg[0][k][1]);
                MMA16816(acc[1], a0, a1, a2, a3, breg[0][k][2], breg[0][k][3]);
            }

            // ---- phase 2: g=1 MMA chain with g=0 EX2 interleaved ----
            float s0 = 0.0f, s1 = 0.0f;
#pragma unroll
            for (int k = 0; k < 8; k++) {
                const int c = 2 * k + aChunkHalf;
                uint32_t a0, a1, a2, a3;
                uint32_t addrA = abuf + aRow * 256 + ((c ^ (aRow & 7)) * 16);
                LDSM_X4(a0, a1, a2, a3, addrA);
                MMA16816(acc[2], a0, a1, a2, a3, breg[1][k][0], breg[1][k][1]);
                MMA16816(acc[3], a0, a1, a2, a3, breg[1][k][2], breg[1][k][3]);
                const int nf = k >> 2;
                const int q  = k & 3;
                float e = ex2_approx(acc[nf][q]);
                if (q < 2) s0 += e; else s1 += e;
            }

            BAR_PAIR(barid);       // release

            // ---- phase 3: remaining EX2 + reduce + store ----
#pragma unroll
            for (int nf = 2; nf < 4; nf++) {
                s0 += ex2_approx(acc[nf][0]) + ex2_approx(acc[nf][1]);
                s1 += ex2_approx(acc[nf][2]) + ex2_approx(acc[nf][3]);
            }
            s0 += __shfl_xor_sync(0xFFFFFFFFu, s0, 1);
            s0 += __shfl_xor_sync(0xFFFFFFFFu, s0, 2);
            s1 += __shfl_xor_sync(0xFFFFFFFFu, s1, 1);
            s1 += __shfl_xor_sync(0xFFFFFFFFu, s1, 2);
            if ((lane & 3) == 0) {
                int r = it * 64 + mwarp + (lane >> 2);
                gpart[r]     = s0;
                gpart[r + 8] = s1;
            }
        }

        // ---- tile boundary: build next tile's sB from staged fp32 ----
        if (!last_tile) {
            const int nb2 = (nt + GRID_G) * BN;
            float4 v[8];
#pragma unroll
            for (int i = 0; i < 8; i++) {
                const int gr = nb2 + r0 + i;
                if (gr < C_CLS)
                    v[i] = *reinterpret_cast<float4*>(stage + (r0 + i) * 512 + lane * 16);
                else
                    v[i] = make_float4(0.f, 0.f, 0.f, 0.f);
            }
            build_sB_rows(sB, v, r0, nb2, lane);
            __syncthreads();       // all sB rows written before breg reload
#pragma unroll
            for (int g = 0; g < 2; g++)
#pragma unroll
                for (int k = 0; k < 8; k++) {
                    uint32_t addrB = (uint32_t)__cvta_generic_to_shared(
                        &sB[(ncb + g * 16 + bRowOff) * LDSB + k * 16 + bColOff]);
                    LDSM_X4(breg[g][k][0], breg[g][k][1], breg[g][k][2], breg[g][k][3], addrB);
                }
        }
    }
}

// ------------------------- reduce: 640 blocks --------------------------------
__global__ void reduce_kernel(const float* __restrict__ xs,
                              const int* __restrict__ ys32,
                              const float* __restrict__ proxies,
                              float* __restrict__ out) {
    __shared__ float red[8][32];
    __shared__ float red2[256];
    __shared__ int   is_last;
    const int w    = threadIdx.x >> 5;
    const int lane = threadIdx.x & 31;

    if (threadIdx.x == 0) is_last = 0;

    if (blockIdx.x >= RED_SLICE_BLKS) {
        const int pb = (blockIdx.x - RED_SLICE_BLKS) * 8 + w;
        int probe = ys32[2 * lane + 1];
        bool is64 = (__ballot_sync(0xFFFFFFFFu, probe != 0) == 0u);
        int y = is64 ? ys32[2 * pb] : ys32[pb];

        float4 xv = reinterpret_cast<const float4*>(xs + (size_t)pb * D_DIM)[lane];
        float4 pv = reinterpret_cast<const float4*>(proxies + (size_t)y * D_DIM)[lane];
        float xsq = xv.x*xv.x + xv.y*xv.y + xv.z*xv.z + xv.w*xv.w;
        float psq = pv.x*pv.x + pv.y*pv.y + pv.z*pv.z + pv.w*pv.w;
        float xp  = xv.x*pv.x + xv.y*pv.y + xv.z*pv.z + xv.w*pv.w;
        xsq = warp_sum(xsq); psq = warp_sum(psq); xp = warp_sum(xp);
        if (lane == 0) {
            float norm = fmaxf(sqrtf(psq), 1e-12f);
            g_dpos[pb] = xsq + 1.0f - 2.0f * xp / norm;
            g_xsq[pb]  = xsq;
        }
        __syncthreads();
        __threadfence();
        if (threadIdx.x == 0) {
            int old = atomicAdd(&g_cnt, 1);
            if (old == RED_TOTAL_BLKS - 1) is_last = 1;
        }
    } else {
        const int bg    = blockIdx.x & 31;
        const int slice = blockIdx.x >> 5;
        const int b     = bg * 32 + lane;

        float s = 0.0f;
        for (int t = slice + 16 * w; t < NTILES; t += 16 * 8) {
            s += g_partA[(size_t)t * B_ROWS + b] + g_partB[(size_t)t * B_ROWS + b];
        }
        red[w][lane] = s;
        __syncthreads();

        if (w == 0) {
            float v = red[0][lane] + red[1][lane] + red[2][lane] + red[3][lane]
                    + red[4][lane] + red[5][lane] + red[6][lane] + red[7][lane];
            g_stage[slice][b] = v;
            __threadfence();
            if (lane == 0) {
                int old = atomicAdd(&g_cnt, 1);
                if (old == RED_TOTAL_BLKS - 1) is_last = 1;
            }
        }
    }
    __syncthreads();

    if (is_last) {
        const int t = threadIdx.x;
        float acc = 0.0f;
#pragma unroll
        for (int q = 0; q < 4; q++) {
            const int bb = t + q * 256;
            float S = 0.0f;
#pragma unroll
            for (int sl = 0; sl < SLICES; sl++) S += g_stage[sl][bb];
            S -= (float)N_PADS;
            float d   = g_dpos[bb];
            float xsq = g_xsq[bb];
            float neg = expf(-xsq - 1.0f) * S - expf(-d);
            acc += d + logf(neg);
        }
        red2[t] = acc;
        __syncthreads();
        for (int k = 128; k > 0; k >>= 1) {
            if (t < k) red2[t] += red2[t + k];
            __syncthreads();
        }
        if (t == 0) out[0] = red2[0] * (1.0f / (float)B_ROWS);
    }
}

// ------------------------- launch -------------------------------------------
extern "C" void kernel_launch(void* const* d_in, const int* in_sizes, int n_in,
                              void* d_out, int out_size) {
    const float* xs = nullptr;
    const int*   ys = nullptr;
    const float* proxies = nullptr;
    for (int i = 0; i < n_in; i++) {
        if (in_sizes[i] == B_ROWS)              ys      = (const int*)d_in[i];
        else if (in_sizes[i] == B_ROWS * D_DIM) xs      = (const float*)d_in[i];
        else if (in_sizes[i] == C_CLS * D_DIM)  proxies = (const float*)d_in[i];
    }
    float* out = (float*)d_out;

    cudaFuncSetAttribute(gemm_kernel,
                         cudaFuncAttributeMaxDynamicSharedMemorySize, SMEM_TOTAL);

    pre_kernel<<<(B_ROWS * D_DIM / 4) / 256, 256>>>(xs);
    gemm_kernel<<<GRID_G, 256, SMEM_TOTAL>>>(proxies);
    reduce_kernel<<<RED_TOTAL_BLKS, 256>>>(xs, ys, proxies, out);
}

// round 16
// speedup vs baseline: 1.0887x; 1.0887x over previous
#include <cuda_runtime.h>
#include <cuda_bf16.h>
#include <cstdint>

// ---------------------------------------------------------------------------
// ProxyNCALoss on GB300 — HMMA path (ptxas stage targets sm_103: no tcgen05).
//   loss_b = d_pos[b] + log( exp(-xsq_b - 1) * (S_b - 32) - exp(-d_pos_b) )
// GEMM M=1024, N=100032 (1563 x 64), K=128, bf16 mma.sync.
// R16 = R14 (90.6us best) with pre_kernel FUSED into the GEMM: blocks 0..127
// convert xs->bf16 and release a flag; all CTAs run the (independent) B
// prologue first and only spin before issuing A-tile-0 cp.asyncs. 2 launches.
// ---------------------------------------------------------------------------

#define C_CLS 100000
#define D_DIM 128
#define B_ROWS 1024

constexpr int BN = 64;
constexpr int NTILES = (C_CLS + BN - 1) / BN;   // 1563
constexpr int N_PADS = NTILES * BN - C_CLS;     // 32
constexpr int W_ITERS = 16;
constexpr int SLICES  = 16;
constexpr int RED_SLICE_BLKS = 32 * SLICES;     // 512
constexpr int RED_POS_BLKS   = 128;
constexpr int RED_TOTAL_BLKS = RED_SLICE_BLKS + RED_POS_BLKS;   // 640
constexpr int CONV_BLKS = 128;                  // GEMM blocks that convert xs

constexpr int LDSB = 136;                       // B smem row pitch (bf16 elems)
constexpr int A_PBUF = 16 * 256;                // 4096
constexpr int A_PREGION = 2 * A_PBUF;           // 8192
constexpr int SMEM_B_OFF = 4 * A_PREGION;       // 32768
constexpr int SMEM_TOTAL = SMEM_B_OFF + BN * LDSB * 2;   // 50176

constexpr float TWO_LOG2E = 2.8853900817779268f;  // 2*log2(e)

// ------------------------- device scratch ----------------------------------
__device__ __nv_bfloat16 g_X[B_ROWS * D_DIM];
__device__ float g_partA[(size_t)NTILES * B_ROWS];   // [tile][b], cols 0-31
__device__ float g_partB[(size_t)NTILES * B_ROWS];   // [tile][b], cols 32-63
__device__ float g_stage[SLICES][B_ROWS];
__device__ float g_dpos[B_ROWS];
__device__ float g_xsq[B_ROWS];
__device__ int   g_cnt   = 0;                        // reduce counter (reset by last block)
__device__ int   g_xflag = 0;                        // xs-conversion flag (reset by last block)

// ------------------------- helpers -----------------------------------------
__device__ __forceinline__ float warp_sum(float v) {
#pragma unroll
    for (int m = 16; m > 0; m >>= 1) v += __shfl_xor_sync(0xFFFFFFFFu, v, m);
    return v;
}
__device__ __forceinline__ float ex2_approx(float x) {
    float r;
    asm("ex2.approx.f32 %0, %1;" : "=f"(r) : "f"(x));
    return r;
}
__device__ __forceinline__ void cp_async16(uint32_t dst, const void* src) {
    asm volatile("cp.async.cg.shared.global [%0], [%1], 16;" :: "r"(dst), "l"(src));
}
#define CP_COMMIT() asm volatile("cp.async.commit_group;" ::: "memory")
#define CP_WAIT0()  asm volatile("cp.async.wait_group 0;" ::: "memory")
#define BAR_PAIR(id) asm volatile("bar.sync %0, 64;" :: "r"(id) : "memory")

#define LDSM_X4(r0, r1, r2, r3, addr) \
    asm volatile("ldmatrix.sync.aligned.m8n8.x4.shared.b16 {%0,%1,%2,%3}, [%4];\n" \
                 : "=r"(r0), "=r"(r1), "=r"(r2), "=r"(r3) : "r"(addr))

#define MMA16816(acc, a0, a1, a2, a3, b0, b1) \
    asm volatile("mma.sync.aligned.m16n8k16.row.col.f32.bf16.bf16.f32 " \
                 "{%0,%1,%2,%3}, {%4,%5,%6,%7}, {%8,%9}, {%0,%1,%2,%3};\n" \
                 : "+f"((acc)[0]), "+f"((acc)[1]), "+f"((acc)[2]), "+f"((acc)[3]) \
                 : "r"(a0), "r"(a1), "r"(a2), "r"(a3), "r"(b0), "r"(b1))

// ------------------------- GEMM + exp2 row-sum ------------------------------
__global__ __launch_bounds__(256, 2) void gemm_kernel(const float* __restrict__ xs,
                                                      const float* __restrict__ proxies) {
    extern __shared__ __align__(16) char smem[];
    __nv_bfloat16* sB = reinterpret_cast<__nv_bfloat16*>(smem + SMEM_B_OFF);
    const uint32_t sbase = (uint32_t)__cvta_generic_to_shared(smem);

    const int tid  = threadIdx.x;
    const int wid  = tid >> 5;
    const int lane = tid & 31;
    const int nt    = blockIdx.x;
    const int nbase = nt * BN;

    const int pair  = wid >> 1;
    const int half  = wid & 1;
    const int mwarp = pair * 16;
    const int ncb   = half * 32;
    const int barid = pair + 1;
    float* gpart = (half ? g_partB : g_partA) + (size_t)nt * B_ROWS;

    const uint32_t ap_base = sbase + pair * A_PREGION;

    // ---- fused xs->bf16 conversion (blocks 0..127, all in wave 1) ----
    if (blockIdx.x < CONV_BLKS) {
        int i = blockIdx.x * 256 + tid;                 // 32768 float4 slots
        float4 v = reinterpret_cast<const float4*>(xs)[i];
        __nv_bfloat162 lo = __floats2bfloat162_rn(v.x, v.y);
        __nv_bfloat162 hi = __floats2bfloat162_rn(v.z, v.w);
        reinterpret_cast<__nv_bfloat162*>(g_X)[2 * i]     = lo;
        reinterpret_cast<__nv_bfloat162*>(g_X)[2 * i + 1] = hi;
        __threadfence();
        __syncthreads();
        if (tid == 0) atomicAdd(&g_xflag, 1);           // release (after fence)
    }

    // ---- B tile: load, L2-normalize, scale by 2*log2e, bf16, into SMEM ----
    // (independent of g_X — overlaps the conversion wave)
    {
        const int r0 = wid * 8;
        float4 v[8];
#pragma unroll
        for (int i = 0; i < 8; i++) {
            const int gr = nbase + r0 + i;
            if (gr < C_CLS) v[i] = reinterpret_cast<const float4*>(proxies + (size_t)gr * D_DIM)[lane];
            else            v[i] = make_float4(0.f, 0.f, 0.f, 0.f);
        }
#pragma unroll
        for (int i = 0; i < 8; i++) {
            const int gr = nbase + r0 + i;
            float sq = warp_sum(v[i].x*v[i].x + v[i].y*v[i].y + v[i].z*v[i].z + v[i].w*v[i].w);
            float rn = TWO_LOG2E * rsqrtf(fmaxf(sq, 1e-24f));
            if (gr >= C_CLS) rn = 0.0f;
            __nv_bfloat162 lo = __floats2bfloat162_rn(v[i].x * rn, v[i].y * rn);
            __nv_bfloat162 hi = __floats2bfloat162_rn(v[i].z * rn, v[i].w * rn);
            uint2 u;
            u.x = *reinterpret_cast<uint32_t*>(&lo);
            u.y = *reinterpret_cast<uint32_t*>(&hi);
            *reinterpret_cast<uint2*>(&sB[(r0 + i) * LDSB + lane * 4]) = u;
        }
    }

    // ---- wait for full g_X, then issue A tile 0 cp.asyncs ----
    if (tid == 0) {
        volatile int* fp = &g_xflag;
        while (*fp < CONV_BLKS) { }
        __threadfence();                                // acquire
    }
    __syncthreads();
    {
        const char* gA = reinterpret_cast<const char*>(g_X) + (size_t)mwarp * 256;
#pragma unroll
        for (int j = 0; j < 4; j++) {
            int idx = lane + 32 * j;
            int r = half * 8 + (idx >> 4);
            int c = idx & 15;
            cp_async16(ap_base + r * 256 + ((c ^ (r & 7)) * 16), gA + r * 256 + c * 16);
        }
        CP_COMMIT();
    }
    __syncthreads();      // B tile visible to all warps

    // ---- load B fragments ONCE into registers ----
    const int bRowOff = (lane & 7) + ((lane >> 4) << 3);
    const int bColOff = ((lane >> 3) & 1) * 8;
    uint32_t breg[2][8][4];
#pragma unroll
    for (int g = 0; g < 2; g++)
#pragma unroll
        for (int k = 0; k < 8; k++) {
            uint32_t addrB = (uint32_t)__cvta_generic_to_shared(
                &sB[(ncb + g * 16 + bRowOff) * LDSB + k * 16 + bColOff]);
            LDSM_X4(breg[g][k][0], breg[g][k][1], breg[g][k][2], breg[g][k][3], addrB);
        }

    const int aRow = lane & 15;
    const int aChunkHalf = lane >> 4;

    // ================= free-running per-PAIR mainloop =================
#pragma unroll 1
    for (int it = 0; it < W_ITERS; it++) {
        const int buf = it & 1;
        CP_WAIT0();
        __syncwarp();
        BAR_PAIR(barid);       // acquire

        if (it + 1 < W_ITERS) {
            const char* gA = reinterpret_cast<const char*>(g_X)
                           + (size_t)((it + 1) * 64 + mwarp) * 256;
            const uint32_t dst = ap_base + (buf ^ 1) * A_PBUF;
#pragma unroll
            for (int j = 0; j < 4; j++) {
                int idx = lane + 32 * j;
                int r = half * 8 + (idx >> 4);
                int c = idx & 15;
                cp_async16(dst + r * 256 + ((c ^ (r & 7)) * 16), gA + r * 256 + c * 16);
            }
            CP_COMMIT();
        }

        const uint32_t abuf = ap_base + buf * A_PBUF;

        float acc[4][4];
#pragma unroll
        for (int nf = 0; nf < 4; nf++)
#pragma unroll
            for (int j = 0; j < 4; j++) acc[nf][j] = 0.0f;

        // ---- phase 1: g=0 MMA chain ----
#pragma unroll
        for (int k = 0; k < 8; k++) {
            const int c = 2 * k + aChunkHalf;
            uint32_t a0, a1, a2, a3;
            uint32_t addrA = abuf + aRow * 256 + ((c ^ (aRow & 7)) * 16);
            LDSM_X4(a0, a1, a2, a3, addrA);
            MMA16816(acc[0], a0, a1, a2, a3, breg[0][k][0], breg[0][k][1]);
            MMA16816(acc[1], a0, a1, a2, a3, breg[0][k][2], breg[0][k][3]);
        }

        // ---- phase 2: g=1 MMA chain with g=0 EX2 interleaved ----
        float s0 = 0.0f, s1 = 0.0f;
#pragma unroll
        for (int k = 0; k < 8; k++) {
            const int c = 2 * k + aChunkHalf;
            uint32_t a0, a1, a2, a3;
            uint32_t addrA = abuf + aRow * 256 + ((c ^ (aRow & 7)) * 16);
            LDSM_X4(a0, a1, a2, a3, addrA);
            MMA16816(acc[2], a0, a1, a2, a3, breg[1][k][0], breg[1][k][1]);
            MMA16816(acc[3], a0, a1, a2, a3, breg[1][k][2], breg[1][k][3]);
            const int nf = k >> 2;
            const int q  = k & 3;
            float e = ex2_approx(acc[nf][q]);   // acc already in exp2 units
            if (q < 2) s0 += e; else s1 += e;
        }

        BAR_PAIR(barid);       // release

        // ---- phase 3: remaining EX2 + reduce + store ----
#pragma unroll
        for (int nf = 2; nf < 4; nf++) {
            s0 += ex2_approx(acc[nf][0]) + ex2_approx(acc[nf][1]);
            s1 += ex2_approx(acc[nf][2]) + ex2_approx(acc[nf][3]);
        }
        s0 += __shfl_xor_sync(0xFFFFFFFFu, s0, 1);
        s0 += __shfl_xor_sync(0xFFFFFFFFu, s0, 2);
        s1 += __shfl_xor_sync(0xFFFFFFFFu, s1, 1);
        s1 += __shfl_xor_sync(0xFFFFFFFFu, s1, 2);
        if ((lane & 3) == 0) {
            int r = it * 64 + mwarp + (lane >> 2);
            gpart[r]     = s0;
            gpart[r + 8] = s1;
        }
    }
}

// ------------------------- reduce: 640 blocks --------------------------------
// Blocks 0..511: slice partial sums. Blocks 512..639: positive term.
// Last block folds, writes out, and resets both counters for graph replay.
__global__ void reduce_kernel(const float* __restrict__ xs,
                              const int* __restrict__ ys32,
                              const float* __restrict__ proxies,
                              float* __restrict__ out) {
    __shared__ float red[8][32];
    __shared__ float red2[256];
    __shared__ int   is_last;
    const int w    = threadIdx.x >> 5;
    const int lane = threadIdx.x & 31;

    if (threadIdx.x == 0) is_last = 0;

    if (blockIdx.x >= RED_SLICE_BLKS) {
        const int pb = (blockIdx.x - RED_SLICE_BLKS) * 8 + w;
        int probe = ys32[2 * lane + 1];
        bool is64 = (__ballot_sync(0xFFFFFFFFu, probe != 0) == 0u);
        int y = is64 ? ys32[2 * pb] : ys32[pb];

        float4 xv = reinterpret_cast<const float4*>(xs + (size_t)pb * D_DIM)[lane];
        float4 pv = reinterpret_cast<const float4*>(proxies + (size_t)y * D_DIM)[lane];
        float xsq = xv.x*xv.x + xv.y*xv.y + xv.z*xv.z + xv.w*xv.w;
        float psq = pv.x*pv.x + pv.y*pv.y + pv.z*pv.z + pv.w*pv.w;
        float xp  = xv.x*pv.x + xv.y*pv.y + xv.z*pv.z + xv.w*pv.w;
        xsq = warp_sum(xsq); psq = warp_sum(psq); xp = warp_sum(xp);
        if (lane == 0) {
            float norm = fmaxf(sqrtf(psq), 1e-12f);
            g_dpos[pb] = xsq + 1.0f - 2.0f * xp / norm;
            g_xsq[pb]  = xsq;
        }
        __syncthreads();
        __threadfence();
        if (threadIdx.x == 0) {
            int old = atomicAdd(&g_cnt, 1);
            if (old == RED_TOTAL_BLKS - 1) is_last = 1;
        }
    } else {
        const int bg    = blockIdx.x & 31;
        const int slice = blockIdx.x >> 5;
        const int b     = bg * 32 + lane;

        float s = 0.0f;
        for (int t = slice + 16 * w; t < NTILES; t += 16 * 8) {
            s += g_partA[(size_t)t * B_ROWS + b] + g_partB[(size_t)t * B_ROWS + b];
        }
        red[w][lane] = s;
        __syncthreads();

        if (w == 0) {
            float v = red[0][lane] + red[1][lane] + red[2][lane] + red[3][lane]
                    + red[4][lane] + red[5][lane] + red[6][lane] + red[7][lane];
            g_stage[slice][b] = v;
            __threadfence();
            if (lane == 0) {
                int old = atomicAdd(&g_cnt, 1);
                if (old == RED_TOTAL_BLKS - 1) is_last = 1;
            }
        }
    }
    __syncthreads();

    if (is_last) {
        const int t = threadIdx.x;
        float acc = 0.0f;
#pragma unroll
        for (int q = 0; q < 4; q++) {
            const int bb = t + q * 256;
            float S = 0.0f;
#pragma unroll
            for (int sl = 0; sl < SLICES; sl++) S += g_stage[sl][bb];
            S -= (float)N_PADS;                 // pad rows contribute exp2(0)=1
            float d   = g_dpos[bb];
            float xsq = g_xsq[bb];
            float neg = expf(-xsq - 1.0f) * S - expf(-d);
            acc += d + logf(neg);
        }
        red2[t] = acc;
        __syncthreads();
        for (int k = 128; k > 0; k >>= 1) {
            if (t < k) red2[t] += red2[t + k];
            __syncthreads();
        }
        if (t == 0) {
            out[0] = red2[0] * (1.0f / (float)B_ROWS);
            g_cnt   = 0;                        // reset for next graph replay
            g_xflag = 0;
        }
    }
}

// ------------------------- launch -------------------------------------------
extern "C" void kernel_launch(void* const* d_in, const int* in_sizes, int n_in,
                              void* d_out, int out_size) {
    const float* xs = nullptr;
    const int*   ys = nullptr;
    const float* proxies = nullptr;
    for (int i = 0; i < n_in; i++) {
        if (in_sizes[i] == B_ROWS)              ys      = (const int*)d_in[i];
        else if (in_sizes[i] == B_ROWS * D_DIM) xs      = (const float*)d_in[i];
        else if (in_sizes[i] == C_CLS * D_DIM)  proxies = (const float*)d_in[i];
    }
    float* out = (float*)d_out;

    cudaFuncSetAttribute(gemm_kernel,
                         cudaFuncAttributeMaxDynamicSharedMemorySize, SMEM_TOTAL);

    gemm_kernel<<<NTILES, 256, SMEM_TOTAL>>>(xs, proxies);
    reduce_kernel<<<RED_TOTAL_BLKS, 256>>>(xs, ys, proxies, out);
}

// round 17
// speedup vs baseline: 1.1362x; 1.0436x over previous
#include <cuda_runtime.h>
#include <cuda_bf16.h>
#include <cstdint>

// ---------------------------------------------------------------------------
// ProxyNCALoss on GB300 — HMMA path (ptxas stage targets sm_103: no tcgen05).
//   loss_b = d_pos[b] + log( exp(-xsq_b - 1) * (S_b - 32) - exp(-d_pos_b) )
// GEMM M=1024, N=100032 (1563 x 64), K=128, bf16 mma.sync.
// R17 = R14 (90.6us best) + MLP-8 unrolled reduce stage 1 (R16 profile showed
// the reduce at 14.6us latency-bound, issue 7.9%, MLP~2). R16's pre-kernel
// fusion reverted (it regressed).
// ---------------------------------------------------------------------------

#define C_CLS 100000
#define D_DIM 128
#define B_ROWS 1024

constexpr int BN = 64;
constexpr int NTILES = (C_CLS + BN - 1) / BN;   // 1563
constexpr int N_PADS = NTILES * BN - C_CLS;     // 32
constexpr int W_ITERS = 16;
constexpr int SLICES  = 16;
constexpr int RED_SLICE_BLKS = 32 * SLICES;     // 512
constexpr int RED_POS_BLKS   = 128;
constexpr int RED_TOTAL_BLKS = RED_SLICE_BLKS + RED_POS_BLKS;   // 640

constexpr int LDSB = 136;                       // B smem row pitch (bf16 elems)
constexpr int A_PBUF = 16 * 256;                // 4096
constexpr int A_PREGION = 2 * A_PBUF;           // 8192
constexpr int SMEM_B_OFF = 4 * A_PREGION;       // 32768
constexpr int SMEM_TOTAL = SMEM_B_OFF + BN * LDSB * 2;   // 50176

constexpr float TWO_LOG2E = 2.8853900817779268f;  // 2*log2(e)

// ------------------------- device scratch ----------------------------------
__device__ __nv_bfloat16 g_X[B_ROWS * D_DIM];
__device__ float g_partA[(size_t)NTILES * B_ROWS];   // [tile][b], cols 0-31
__device__ float g_partB[(size_t)NTILES * B_ROWS];   // [tile][b], cols 32-63
__device__ float g_stage[SLICES][B_ROWS];
__device__ float g_dpos[B_ROWS];
__device__ float g_xsq[B_ROWS];
__device__ int   g_cnt;

// ------------------------- helpers -----------------------------------------
__device__ __forceinline__ float warp_sum(float v) {
#pragma unroll
    for (int m = 16; m > 0; m >>= 1) v += __shfl_xor_sync(0xFFFFFFFFu, v, m);
    return v;
}
__device__ __forceinline__ float ex2_approx(float x) {
    float r;
    asm("ex2.approx.f32 %0, %1;" : "=f"(r) : "f"(x));
    return r;
}
__device__ __forceinline__ void cp_async16(uint32_t dst, const void* src) {
    asm volatile("cp.async.cg.shared.global [%0], [%1], 16;" :: "r"(dst), "l"(src));
}
#define CP_COMMIT() asm volatile("cp.async.commit_group;" ::: "memory")
#define CP_WAIT0()  asm volatile("cp.async.wait_group 0;" ::: "memory")
#define BAR_PAIR(id) asm volatile("bar.sync %0, 64;" :: "r"(id) : "memory")

#define LDSM_X4(r0, r1, r2, r3, addr) \
    asm volatile("ldmatrix.sync.aligned.m8n8.x4.shared.b16 {%0,%1,%2,%3}, [%4];\n" \
                 : "=r"(r0), "=r"(r1), "=r"(r2), "=r"(r3) : "r"(addr))

#define MMA16816(acc, a0, a1, a2, a3, b0, b1) \
    asm volatile("mma.sync.aligned.m16n8k16.row.col.f32.bf16.bf16.f32 " \
                 "{%0,%1,%2,%3}, {%4,%5,%6,%7}, {%8,%9}, {%0,%1,%2,%3};\n" \
                 : "+f"((acc)[0]), "+f"((acc)[1]), "+f"((acc)[2]), "+f"((acc)[3]) \
                 : "r"(a0), "r"(a1), "r"(a2), "r"(a3), "r"(b0), "r"(b1))

// ------------------------- pre-kernel: xs -> bf16 only ----------------------
__global__ void pre_kernel(const float* __restrict__ xs) {
    if (blockIdx.x == 0 && threadIdx.x == 0) g_cnt = 0;
    int i = blockIdx.x * blockDim.x + threadIdx.x;
    float4 v = reinterpret_cast<const float4*>(xs)[i];
    __nv_bfloat162 lo = __floats2bfloat162_rn(v.x, v.y);
    __nv_bfloat162 hi = __floats2bfloat162_rn(v.z, v.w);
    reinterpret_cast<__nv_bfloat162*>(g_X)[2 * i]     = lo;
    reinterpret_cast<__nv_bfloat162*>(g_X)[2 * i + 1] = hi;
}

// ------------------------- GEMM + exp2 row-sum ------------------------------
__global__ __launch_bounds__(256, 2) void gemm_kernel(const float* __restrict__ proxies) {
    extern __shared__ __align__(16) char smem[];
    __nv_bfloat16* sB = reinterpret_cast<__nv_bfloat16*>(smem + SMEM_B_OFF);
    const uint32_t sbase = (uint32_t)__cvta_generic_to_shared(smem);

    const int tid  = threadIdx.x;
    const int wid  = tid >> 5;
    const int lane = tid & 31;
    const int nt    = blockIdx.x;
    const int nbase = nt * BN;

    const int pair  = wid >> 1;
    const int half  = wid & 1;
    const int mwarp = pair * 16;
    const int ncb   = half * 32;
    const int barid = pair + 1;
    float* gpart = (half ? g_partB : g_partA) + (size_t)nt * B_ROWS;

    const uint32_t ap_base = sbase + pair * A_PREGION;

    // ---- prologue: this warp's HALF of A tile 0 ----
    {
        const char* gA = reinterpret_cast<const char*>(g_X) + (size_t)mwarp * 256;
#pragma unroll
        for (int j = 0; j < 4; j++) {
            int idx = lane + 32 * j;
            int r = half * 8 + (idx >> 4);
            int c = idx & 15;
            cp_async16(ap_base + r * 256 + ((c ^ (r & 7)) * 16), gA + r * 256 + c * 16);
        }
        CP_COMMIT();
    }

    // ---- B tile: load, L2-normalize, scale by 2*log2e, bf16, into SMEM ----
    {
        const int r0 = wid * 8;
        float4 v[8];
#pragma unroll
        for (int i = 0; i < 8; i++) {
            const int gr = nbase + r0 + i;
            if (gr < C_CLS) v[i] = reinterpret_cast<const float4*>(proxies + (size_t)gr * D_DIM)[lane];
            else            v[i] = make_float4(0.f, 0.f, 0.f, 0.f);
        }
#pragma unroll
        for (int i = 0; i < 8; i++) {
            const int gr = nbase + r0 + i;
            float sq = warp_sum(v[i].x*v[i].x + v[i].y*v[i].y + v[i].z*v[i].z + v[i].w*v[i].w);
            float rn = TWO_LOG2E * rsqrtf(fmaxf(sq, 1e-24f));
            if (gr >= C_CLS) rn = 0.0f;
            __nv_bfloat162 lo = __floats2bfloat162_rn(v[i].x * rn, v[i].y * rn);
            __nv_bfloat162 hi = __floats2bfloat162_rn(v[i].z * rn, v[i].w * rn);
            uint2 u;
            u.x = *reinterpret_cast<uint32_t*>(&lo);
            u.y = *reinterpret_cast<uint32_t*>(&hi);
            *reinterpret_cast<uint2*>(&sB[(r0 + i) * LDSB + lane * 4]) = u;
        }
    }
    __syncthreads();      // B tile visible to all warps

    // ---- load B fragments ONCE into registers ----
    const int bRowOff = (lane & 7) + ((lane >> 4) << 3);
    const int bColOff = ((lane >> 3) & 1) * 8;
    uint32_t breg[2][8][4];
#pragma unroll
    for (int g = 0; g < 2; g++)
#pragma unroll
        for (int k = 0; k < 8; k++) {
            uint32_t addrB = (uint32_t)__cvta_generic_to_shared(
                &sB[(ncb + g * 16 + bRowOff) * LDSB + k * 16 + bColOff]);
            LDSM_X4(breg[g][k][0], breg[g][k][1], breg[g][k][2], breg[g][k][3], addrB);
        }

    const int aRow = lane & 15;
    const int aChunkHalf = lane >> 4;

    // ================= free-running per-PAIR mainloop =================
#pragma unroll 1
    for (int it = 0; it < W_ITERS; it++) {
        const int buf = it & 1;
        CP_WAIT0();
        __syncwarp();
        BAR_PAIR(barid);       // acquire

        if (it + 1 < W_ITERS) {
            const char* gA = reinterpret_cast<const char*>(g_X)
                           + (size_t)((it + 1) * 64 + mwarp) * 256;
            const uint32_t dst = ap_base + (buf ^ 1) * A_PBUF;
#pragma unroll
            for (int j = 0; j < 4; j++) {
                int idx = lane + 32 * j;
                int r = half * 8 + (idx >> 4);
                int c = idx & 15;
                cp_async16(dst + r * 256 + ((c ^ (r & 7)) * 16), gA + r * 256 + c * 16);
            }
            CP_COMMIT();
        }

        const uint32_t abuf = ap_base + buf * A_PBUF;

        float acc[4][4];
#pragma unroll
        for (int nf = 0; nf < 4; nf++)
#pragma unroll
            for (int j = 0; j < 4; j++) acc[nf][j] = 0.0f;

        // ---- phase 1: g=0 MMA chain ----
#pragma unroll
        for (int k = 0; k < 8; k++) {
            const int c = 2 * k + aChunkHalf;
            uint32_t a0, a1, a2, a3;
            uint32_t addrA = abuf + aRow * 256 + ((c ^ (aRow & 7)) * 16);
            LDSM_X4(a0, a1, a2, a3, addrA);
            MMA16816(acc[0], a0, a1, a2, a3, breg[0][k][0], breg[0][k][1]);
            MMA16816(acc[1], a0, a1, a2, a3, breg[0][k][2], breg[0][k][3]);
        }

        // ---- phase 2: g=1 MMA chain with g=0 EX2 interleaved ----
        float s0 = 0.0f, s1 = 0.0f;
#pragma unroll
        for (int k = 0; k < 8; k++) {
            const int c = 2 * k + aChunkHalf;
            uint32_t a0, a1, a2, a3;
            uint32_t addrA = abuf + aRow * 256 + ((c ^ (aRow & 7)) * 16);
            LDSM_X4(a0, a1, a2, a3, addrA);
            MMA16816(acc[2], a0, a1, a2, a3, breg[1][k][0], breg[1][k][1]);
            MMA16816(acc[3], a0, a1, a2, a3, breg[1][k][2], breg[1][k][3]);
            const int nf = k >> 2;
            const int q  = k & 3;
            float e = ex2_approx(acc[nf][q]);   // acc already in exp2 units
            if (q < 2) s0 += e; else s1 += e;
        }

        BAR_PAIR(barid);       // release

        // ---- phase 3: remaining EX2 + reduce + store ----
#pragma unroll
        for (int nf = 2; nf < 4; nf++) {
            s0 += ex2_approx(acc[nf][0]) + ex2_approx(acc[nf][1]);
            s1 += ex2_approx(acc[nf][2]) + ex2_approx(acc[nf][3]);
        }
        s0 += __shfl_xor_sync(0xFFFFFFFFu, s0, 1);
        s0 += __shfl_xor_sync(0xFFFFFFFFu, s0, 2);
        s1 += __shfl_xor_sync(0xFFFFFFFFu, s1, 1);
        s1 += __shfl_xor_sync(0xFFFFFFFFu, s1, 2);
        if ((lane & 3) == 0) {
            int r = it * 64 + mwarp + (lane >> 2);
            gpart[r]     = s0;
            gpart[r + 8] = s1;
        }
    }
}

// ------------------------- reduce: 640 blocks, MLP-8 stage 1 ----------------
__global__ void reduce_kernel(const float* __restrict__ xs,
                              const int* __restrict__ ys32,
                              const float* __restrict__ proxies,
                              float* __restrict__ out) {
    __shared__ float red[8][32];
    __shared__ float red2[256];
    __shared__ int   is_last;
    const int w    = threadIdx.x >> 5;
    const int lane = threadIdx.x & 31;

    if (threadIdx.x == 0) is_last = 0;

    if (blockIdx.x >= RED_SLICE_BLKS) {
        // ---- positive-term block: 8 rows, one warp each ----
        const int pb = (blockIdx.x - RED_SLICE_BLKS) * 8 + w;
        int probe = ys32[2 * lane + 1];
        bool is64 = (__ballot_sync(0xFFFFFFFFu, probe != 0) == 0u);
        int y = is64 ? ys32[2 * pb] : ys32[pb];

        float4 xv = reinterpret_cast<const float4*>(xs + (size_t)pb * D_DIM)[lane];
        float4 pv = reinterpret_cast<const float4*>(proxies + (size_t)y * D_DIM)[lane];
        float xsq = xv.x*xv.x + xv.y*xv.y + xv.z*xv.z + xv.w*xv.w;
        float psq = pv.x*pv.x + pv.y*pv.y + pv.z*pv.z + pv.w*pv.w;
        float xp  = xv.x*pv.x + xv.y*pv.y + xv.z*pv.z + xv.w*pv.w;
        xsq = warp_sum(xsq); psq = warp_sum(psq); xp = warp_sum(xp);
        if (lane == 0) {
            float norm = fmaxf(sqrtf(psq), 1e-12f);
            g_dpos[pb] = xsq + 1.0f - 2.0f * xp / norm;
            g_xsq[pb]  = xsq;
        }
        __syncthreads();
        __threadfence();
        if (threadIdx.x == 0) {
            int old = atomicAdd(&g_cnt, 1);
            if (old == RED_TOTAL_BLKS - 1) is_last = 1;
        }
    } else {
        // ---- slice block: MLP-8 unrolled partial sums (4 indep accumulators)
        const int bg    = blockIdx.x & 31;
        const int slice = blockIdx.x >> 5;
        const int b     = bg * 32 + lane;

        float sa0 = 0.f, sa1 = 0.f, sa2 = 0.f, sa3 = 0.f;
        int t = slice + 16 * w;
#pragma unroll 1
        for (; t + 384 < NTILES; t += 512) {
            // 8 independent LDGs batched per body (MLP=8)
            float a0 = g_partA[(size_t)t * B_ROWS + b];
            float b0 = g_partB[(size_t)t * B_ROWS + b];
            float a1 = g_partA[(size_t)(t + 128) * B_ROWS + b];
            float b1 = g_partB[(size_t)(t + 128) * B_ROWS + b];
            float a2 = g_partA[(size_t)(t + 256) * B_ROWS + b];
            float b2 = g_partB[(size_t)(t + 256) * B_ROWS + b];
            float a3 = g_partA[(size_t)(t + 384) * B_ROWS + b];
            float b3 = g_partB[(size_t)(t + 384) * B_ROWS + b];
            sa0 += a0 + b0;
            sa1 += a1 + b1;
            sa2 += a2 + b2;
            sa3 += a3 + b3;
        }
#pragma unroll 1
        for (; t < NTILES; t += 128)
            sa0 += g_partA[(size_t)t * B_ROWS + b] + g_partB[(size_t)t * B_ROWS + b];

        red[w][lane] = (sa0 + sa1) + (sa2 + sa3);
        __syncthreads();

        if (w == 0) {
            float v = red[0][lane] + red[1][lane] + red[2][lane] + red[3][lane]
                    + red[4][lane] + red[5][lane] + red[6][lane] + red[7][lane];
            g_stage[slice][b] = v;
            __threadfence();
            if (lane == 0) {
                int old = atomicAdd(&g_cnt, 1);
                if (old == RED_TOTAL_BLKS - 1) is_last = 1;
            }
        }
    }
    __syncthreads();

    if (is_last) {
        const int t = threadIdx.x;
        float acc = 0.0f;
#pragma unroll
        for (int q = 0; q < 4; q++) {
            const int bb = t + q * 256;
            float S = 0.0f;
#pragma unroll
            for (int sl = 0; sl < SLICES; sl++) S += g_stage[sl][bb];
            S -= (float)N_PADS;                 // pad rows contribute exp2(0)=1
            float d   = g_dpos[bb];
            float xsq = g_xsq[bb];
            float neg = expf(-xsq - 1.0f) * S - expf(-d);
            acc += d + logf(neg);
        }
        red2[t] = acc;
        __syncthreads();
        for (int k = 128; k > 0; k >>= 1) {
            if (t < k) red2[t] += red2[t + k];
            __syncthreads();
        }
        if (t == 0) out[0] = red2[0] * (1.0f / (float)B_ROWS);
    }
}

// ------------------------- launch -------------------------------------------
extern "C" void kernel_launch(void* const* d_in, const int* in_sizes, int n_in,
                              void* d_out, int out_size) {
    const float* xs = nullptr;
    const int*   ys = nullptr;
    const float* proxies = nullptr;
    for (int i = 0; i < n_in; i++) {
        if (in_sizes[i] == B_ROWS)              ys      = (const int*)d_in[i];
        else if (in_sizes[i] == B_ROWS * D_DIM) xs      = (const float*)d_in[i];
        else if (in_sizes[i] == C_CLS * D_DIM)  proxies = (const float*)d_in[i];
    }
    float* out = (float*)d_out;

    cudaFuncSetAttribute(gemm_kernel,
                         cudaFuncAttributeMaxDynamicSharedMemorySize, SMEM_TOTAL);

    pre_kernel<<<(B_ROWS * D_DIM / 4) / 256, 256>>>(xs);
    gemm_kernel<<<NTILES, 256, SMEM_TOTAL>>>(proxies);
    reduce_kernel<<<RED_TOTAL_BLKS, 256>>>(xs, ys, proxies, out);
}